// round 9
// baseline (speedup 1.0000x reference)
#include <cuda_runtime.h>
#include <stdint.h>
#include <math.h>

#define NCAM 12
#define CIN 256
#define FH 32
#define FW 88
#define HW 2816
#define DBINS 41
#define CTXC 32
#define NB 2
#define BCIN 192
#define BEV 400
#define BMID 64
#define BEVHW 160000

// ---------------- scratch (device globals; no allocations) ----------------
// B-frag arrays, PAIR-PACKED: float4 @ ((k8*32 + lane)*(NF/2) + p) = {b0,b1 of fn=2p, b0,b1 of fn=2p+1}
__device__ __align__(16) float g_w1d[288*32*32*2];
__device__ __align__(16) float g_w1c[288*32*32*2];
__device__ __align__(16) float g_w1b[216*8*32*2];
__device__ __align__(16) float g_w2d[32*8*32*2];
__device__ __align__(16) float g_w2c[32*8*32*2];
__device__ __align__(16) float g_w2b[8*8*32*2];
__device__ __align__(16) float g_hidA[(size_t)2*NCAM*22*128*256];
__device__ __align__(16) float g_context[NCAM*CTXC*HW];
__device__ __align__(16) float g_bev[(size_t)NB*BCIN*BEVHW];
__device__ __align__(16) float g_featr[(size_t)NCAM*CIN*HW];   // tf32-rounded feat

// ---------------- helpers ----------------
__device__ __forceinline__ uint32_t f2tf32(float x){
    uint32_t r; asm("cvt.rna.tf32.f32 %0, %1;" : "=r"(r) : "f"(x)); return r;
}
__device__ __forceinline__ float to_tf32(float x){ return __uint_as_float(f2tf32(x)); }
__device__ __forceinline__ void mma8(float4& d,
    uint32_t a0, uint32_t a1, uint32_t a2, uint32_t a3,
    uint32_t b0, uint32_t b1)
{
    asm volatile("mma.sync.aligned.m16n8k8.row.col.f32.tf32.tf32.f32 "
        "{%0,%1,%2,%3}, {%4,%5,%6,%7}, {%8,%9}, {%0,%1,%2,%3};"
        : "+f"(d.x), "+f"(d.y), "+f"(d.z), "+f"(d.w)
        : "r"(a0), "r"(a1), "r"(a2), "r"(a3), "r"(b0), "r"(b1));
}

// ============ prep 1: conv3x3 weights -> PAIR-PACKED B-frag order ============
// k = t*IC + ic. l=(oc&7)*4+(k&3), pos=(k&7)>>2, fn=oc>>3, pair p=fn>>1
// out[ (((k>>3)*32 + l)*(NF>>1) + (fn>>1))*4 + (fn&1)*2 + pos ]
__global__ void prep_big(const float* __restrict__ dw1, const float* __restrict__ cw1,
                         const float* __restrict__ bw1)
{
    const int y = blockIdx.y;
    const float* w; float* o; int OC, IC;
    if (y == 0){ w = dw1; o = g_w1d; OC = 256; IC = 256; }
    else if (y == 1){ w = cw1; o = g_w1c; OC = 256; IC = 256; }
    else { w = bw1; o = g_w1b; OC = 64; IC = 192; }
    int idx = blockIdx.x*256 + threadIdx.x;
    if (idx >= OC*IC*9) return;
    int oc = idx / (IC*9);
    int rr = idx - oc*(IC*9);
    int ic = rr / 9;
    int t  = rr - ic*9;
    int k  = t*IC + ic;
    int NF = OC >> 3;
    int fn = oc >> 3;
    int l = (oc & 7)*4 + (k & 3);
    int pos = (k & 7) >> 2;
    o[((((size_t)(k>>3)*32 + l)*(NF>>1) + (fn>>1))*4) + (fn&1)*2 + pos] = to_tf32(w[idx]);
}

// ============ prep 2: 1x1 weights -> pair-packed frags (padded to 64) + feat rounding ============
__global__ void prep_small(const float* __restrict__ dw2, const float* __restrict__ cw2,
                           const float* __restrict__ bw2, const float* __restrict__ feat)
{
    const int y = blockIdx.y;
    if (y == 3){
        int i = blockIdx.x*256 + threadIdx.x;        // float4 index
        if (i < (NCAM*CIN*HW)/4){
            float4 v = __ldg(reinterpret_cast<const float4*>(feat) + i);
            v.x = to_tf32(v.x); v.y = to_tf32(v.y);
            v.z = to_tf32(v.z); v.w = to_tf32(v.w);
            reinterpret_cast<float4*>(g_featr)[i] = v;
        }
        return;
    }
    const float* w; float* o; int OC, K;
    if (y == 0){ w = dw2; o = g_w2d; OC = DBINS; K = 256; }
    else if (y == 1){ w = cw2; o = g_w2c; OC = CTXC; K = 256; }
    else { w = bw2; o = g_w2b; OC = 64; K = 64; }
    int idx = blockIdx.x*256 + threadIdx.x;
    if (idx >= 64*K) return;
    int oc = idx / K, k = idx - oc*K;
    float v = (oc < OC) ? to_tf32(w[(size_t)oc*K + k]) : 0.f;
    int fn = oc >> 3;                                  // NF = 8, 4 pairs
    int l = (oc & 7)*4 + (k & 3);
    int pos = (k & 7) >> 2;
    o[((((size_t)(k>>3)*32 + l)*4 + (fn>>1))*4) + (fn&1)*2 + pos] = v;
}

// ============ HEAD conv3x3 + BN + ReLU -> g_hidA (frag order) ============
// grid (22, 12, 2), 512 threads. M=128 px, N=256, K=2304 (72 chunks of 32).
__global__ __launch_bounds__(512) void head3_mma(
    const float* __restrict__ db1, const float* __restrict__ dg,
    const float* __restrict__ dbt, const float* __restrict__ dm, const float* __restrict__ dv,
    const float* __restrict__ cb1, const float* __restrict__ cg,
    const float* __restrict__ cbt, const float* __restrict__ cm, const float* __restrict__ cv)
{
    __shared__ __align__(16) float Abuf[2][4096];
    __shared__ float sS[256], sT[256];

    const int tid = threadIdx.x;
    const int pb = blockIdx.x, n = blockIdx.y, head = blockIdx.z;
    const float* W1 = head ? g_w1c : g_w1d;

    if (tid < 256){
        int c = tid;
        float gam = head ? cg[c]  : dg[c];
        float var = head ? cv[c]  : dv[c];
        float bet = head ? cbt[c] : dbt[c];
        float mu  = head ? cm[c]  : dm[c];
        float bi  = head ? cb1[c] : db1[c];
        float s = gam * rsqrtf(var + 1e-5f);
        sS[c] = s;
        sT[c] = bet + (bi - mu)*s;
    }

    const int lane = tid & 31;
    const int wrp  = tid >> 5;
    const int wm = wrp & 3;          // m-warp: fm = wm*2 + mi
    const int wn = wrp >> 2;         // n-warp: fn = wn*8 + j (pairs wn*4 + jp)

    // staging precompute: 2 slots per thread, 9-bit tap-validity masks
    int sOff0[2], sOff1[2], sIc[2], sSlot[2];
    uint32_t mA[2], mB[2];
#pragma unroll
    for (int i = 0; i < 2; i++){
        int s = tid + i*512;
        int fm = s >> 7, fk = (s >> 5) & 3, l = s & 31;
        int m0 = fm*16 + (l >> 2);
        int px0 = pb*128 + m0, px1 = px0 + 8;
        int h0 = px0 / FW, w0 = px0 % FW;
        int h1 = px1 / FW, w1 = px1 % FW;
        sOff0[i] = px0; sOff1[i] = px1;
        sIc[i] = fk*8 + (l & 3);
        sSlot[i] = s;
        mA[i] = 0; mB[i] = 0;
#pragma unroll
        for (int t = 0; t < 9; t++){
            int dy = t/3 - 1, dx = t - (t/3)*3 - 1;
            if ((unsigned)(h0+dy) < FH && (unsigned)(w0+dx) < FW) mA[i] |= 1u << t;
            if ((unsigned)(h1+dy) < FH && (unsigned)(w1+dx) < FW) mB[i] |= 1u << t;
        }
    }

    float4 acc[2][8];
#pragma unroll
    for (int mi = 0; mi < 2; mi++)
#pragma unroll
        for (int j = 0; j < 8; j++) acc[mi][j] = make_float4(0.f,0.f,0.f,0.f);

    float pv[2][4];
    auto gather = [&](int ch){
        int t = ch >> 3, icb = ch & 7;
        int dy = t/3 - 1, dx = t - (t/3)*3 - 1;
        int doff = dy*FW + dx;
#pragma unroll
        for (int i = 0; i < 2; i++){
            const float* base = g_featr + ((size_t)n*CIN + icb*32 + sIc[i])*HW;
            bool ok0 = (mA[i] >> t) & 1;
            bool ok1 = (mB[i] >> t) & 1;
            int o0 = sOff0[i] + doff, o1 = sOff1[i] + doff;
            pv[i][0] = ok0 ? __ldg(base + o0) : 0.f;
            pv[i][1] = ok1 ? __ldg(base + o1) : 0.f;
            pv[i][2] = ok0 ? __ldg(base + 4*HW + o0) : 0.f;
            pv[i][3] = ok1 ? __ldg(base + 4*HW + o1) : 0.f;
        }
    };
    auto store_stage = [&](int buf){
#pragma unroll
        for (int i = 0; i < 2; i++)
            *reinterpret_cast<float4*>(&Abuf[buf][sSlot[i]*4]) =
                make_float4(pv[i][0], pv[i][1], pv[i][2], pv[i][3]);
    };

    gather(0);
    store_stage(0);
    __syncthreads();

    for (int ch = 0; ch < 72; ch++){
        if (ch < 71) gather(ch + 1);
        const float4* Af = reinterpret_cast<const float4*>(&Abuf[ch & 1][0]);
        const float4* Bbase = reinterpret_cast<const float4*>(W1);
#pragma unroll
        for (int fk = 0; fk < 4; fk++){
            int k8g = ch*4 + fk;
            uint32_t a[2][4];
#pragma unroll
            for (int mi = 0; mi < 2; mi++){
                float4 av = Af[((wm*2 + mi)*4 + fk)*32 + lane];
                a[mi][0] = __float_as_uint(av.x); a[mi][1] = __float_as_uint(av.y);
                a[mi][2] = __float_as_uint(av.z); a[mi][3] = __float_as_uint(av.w);
            }
            // pair-packed: 4 LDG.128 cover 8 fn
            const float4* Bf = Bbase + ((size_t)k8g*32 + lane)*16 + wn*4;
#pragma unroll
            for (int jp = 0; jp < 4; jp++){
                float4 bv = __ldg(Bf + jp);
                uint32_t b0 = __float_as_uint(bv.x), b1 = __float_as_uint(bv.y);
                uint32_t b2 = __float_as_uint(bv.z), b3 = __float_as_uint(bv.w);
                mma8(acc[0][jp*2],   a[0][0],a[0][1],a[0][2],a[0][3], b0,b1);
                mma8(acc[1][jp*2],   a[1][0],a[1][1],a[1][2],a[1][3], b0,b1);
                mma8(acc[0][jp*2+1], a[0][0],a[0][1],a[0][2],a[0][3], b2,b3);
                mma8(acc[1][jp*2+1], a[1][0],a[1][1],a[1][2],a[1][3], b2,b3);
            }
        }
        if (ch < 71) store_stage((ch + 1) & 1);
        __syncthreads();
    }

    // epilogue: BN + ReLU, write in stage-2 A-fragment order
    const int g4 = lane >> 2, t4 = lane & 3;
    float* dst = g_hidA + ((size_t)(head*NCAM + n)*22 + pb)*32768;
#pragma unroll
    for (int mi = 0; mi < 2; mi++){
        int fm = wm*2 + mi;
#pragma unroll
        for (int j = 0; j < 8; j++){
            int fn = wn*8 + j;
            float v[4] = {acc[mi][j].x, acc[mi][j].y, acc[mi][j].z, acc[mi][j].w};
#pragma unroll
            for (int q = 0; q < 4; q++){
                int oc = fn*8 + 2*t4 + (q & 1);
                int r2 = g4 + (q >> 1)*8;
                float val = fmaxf(fmaf(v[q], sS[oc], sT[oc]), 0.f);
                int l2  = g4*4 + (oc & 3);
                int pos = (r2 >> 3) + 2*((oc & 7) >> 2);
                dst[(size_t)((fn*8 + fm)*32 + l2)*4 + pos] = to_tf32(val);
            }
        }
    }
}

// ============ HEAD 1x1 (256 -> 41/32), reads g_hidA frags directly ============
__global__ __launch_bounds__(256) void head1_mma(
    const float* __restrict__ db2, const float* __restrict__ cb2,
    float* __restrict__ depth_out)
{
    const int tid = threadIdx.x;
    const int pb = blockIdx.x, n = blockIdx.y, head = blockIdx.z;
    const int lane = tid & 31, wrp = tid >> 5;
    const int wm = wrp & 3, wn = wrp >> 2;   // fn = wn*4 + j, pairs wn*2 + jp

    const float* W2 = head ? g_w2c : g_w2d;
    const float* Ab = g_hidA + ((size_t)(head*NCAM + n)*22 + pb)*32768;

    float4 acc[2][4];
#pragma unroll
    for (int mi = 0; mi < 2; mi++)
#pragma unroll
        for (int j = 0; j < 4; j++) acc[mi][j] = make_float4(0.f,0.f,0.f,0.f);

#pragma unroll 4
    for (int k8 = 0; k8 < 32; k8++){
        uint32_t a[2][4];
#pragma unroll
        for (int mi = 0; mi < 2; mi++){
            float4 av = __ldg(reinterpret_cast<const float4*>(Ab) +
                              (k8*8 + wm*2 + mi)*32 + lane);
            a[mi][0] = __float_as_uint(av.x); a[mi][1] = __float_as_uint(av.y);
            a[mi][2] = __float_as_uint(av.z); a[mi][3] = __float_as_uint(av.w);
        }
        const float4* Bf = reinterpret_cast<const float4*>(W2) +
                           ((size_t)k8*32 + lane)*4 + wn*2;
#pragma unroll
        for (int jp = 0; jp < 2; jp++){
            float4 bv = __ldg(Bf + jp);
            uint32_t b0 = __float_as_uint(bv.x), b1 = __float_as_uint(bv.y);
            uint32_t b2 = __float_as_uint(bv.z), b3 = __float_as_uint(bv.w);
            mma8(acc[0][jp*2],   a[0][0],a[0][1],a[0][2],a[0][3], b0,b1);
            mma8(acc[1][jp*2],   a[1][0],a[1][1],a[1][2],a[1][3], b0,b1);
            mma8(acc[0][jp*2+1], a[0][0],a[0][1],a[0][2],a[0][3], b2,b3);
            mma8(acc[1][jp*2+1], a[1][0],a[1][1],a[1][2],a[1][3], b2,b3);
        }
    }

    const int g4 = lane >> 2, t4 = lane & 3;
#pragma unroll
    for (int mi = 0; mi < 2; mi++){
        int fm = wm*2 + mi;
#pragma unroll
        for (int j = 0; j < 4; j++){
            int fn = wn*4 + j;
            float v[4] = {acc[mi][j].x, acc[mi][j].y, acc[mi][j].z, acc[mi][j].w};
#pragma unroll
            for (int q = 0; q < 4; q++){
                int oc = fn*8 + 2*t4 + (q & 1);
                int px = pb*128 + fm*16 + g4 + (q >> 1)*8;
                if (head == 0){
                    if (oc < DBINS)
                        depth_out[((size_t)n*DBINS + oc)*HW + px] = v[q] + __ldg(db2 + oc);
                } else {
                    if (oc < CTXC)
                        g_context[((size_t)n*CTXC + oc)*HW + px] = v[q] + __ldg(cb2 + oc);
                }
            }
        }
    }
}

// ============ bilinear upsample (half-pixel, clamp), writes tf32-rounded ============
__global__ __launch_bounds__(256) void upsample_k()
{
    long idx = (long)blockIdx.x * 256 + threadIdx.x;
    const long total = (long)NB*BCIN*BEV*100;
    if (idx >= total) return;
    int q = (int)(idx % 100);
    long rr = idx / 100;
    int i = (int)(rr % BEV);  rr /= BEV;
    int g = (int)(rr % BCIN);
    int b = (int)(rr / BCIN);

    float sy = (i + 0.5f) * (32.f/400.f) - 0.5f;
    int y0 = (int)floorf(sy); float fy = sy - (float)y0;
    int y1 = y0 + 1;
    y0 = max(0, min(FH-1, y0)); y1 = max(0, min(FH-1, y1));
    const float* p0 = g_context + ((long)b*BCIN + g)*HW + y0*FW;
    const float* p1 = g_context + ((long)b*BCIN + g)*HW + y1*FW;

    float4 o; float* ov = &o.x;
#pragma unroll
    for (int c = 0; c < 4; c++){
        int j = q*4 + c;
        float sx = (j + 0.5f) * (88.f/400.f) - 0.5f;
        int x0 = (int)floorf(sx); float fx = sx - (float)x0;
        int x1 = x0 + 1;
        x0 = max(0, min(FW-1, x0)); x1 = max(0, min(FW-1, x1));
        float t  = p0[x0] + (p0[x1] - p0[x0]) * fx;
        float bo = p1[x0] + (p1[x1] - p1[x0]) * fx;
        ov[c] = to_tf32(t + (bo - t) * fy);
    }
    *reinterpret_cast<float4*>(&g_bev[(((long)b*BCIN + g)*BEV + i)*BEV + q*4]) = o;
}

// ============ BEV conv3x3 + GELU + 1x1, fused mma ============
// grid (13, 50, 2), 512 threads. Tile = 8 rows x 32 cols = 256 px. N=64, K=1728.
__global__ __launch_bounds__(512) void bev_mma(
    const float* __restrict__ bb1, const float* __restrict__ bb2,
    float* __restrict__ out)
{
    extern __shared__ __align__(16) float sbuf[];
    float* Ast0 = sbuf;
    float* Ast1 = sbuf + 8192;

    const int tid = threadIdx.x;
    const int wb = blockIdx.x, hb = blockIdx.y, b = blockIdx.z;
    const int lane = tid & 31, wrp = tid >> 5;
    const int wm = wrp & 3;          // m-warp: fm = wm*4 + mi (mi 0..3)
    const int wn = wrp >> 2;         // n-warp 0..3: fn = wn*2 + j -> pair p = wn

    // staging precompute: 4 slots per thread (2048 slots total)
    int sO0[4], sO1[4], sC[4], sSlot[4];
    uint32_t mA[4], mB[4];
#pragma unroll
    for (int i = 0; i < 4; i++){
        int s = tid + i*512;
        int fm = s >> 7, fk = (s >> 5) & 3, l = s & 31;
        int m0 = fm*16 + (l >> 2), m1 = m0 + 8;
        int h0 = hb*8 + (m0 >> 5), w0 = wb*32 + (m0 & 31);
        int h1 = hb*8 + (m1 >> 5), w1 = wb*32 + (m1 & 31);
        sO0[i] = h0*BEV + w0; sO1[i] = h1*BEV + w1;
        sC[i] = (fk*8 + (l & 3))*BEVHW;
        sSlot[i] = s;
        mA[i] = 0; mB[i] = 0;
#pragma unroll
        for (int t = 0; t < 9; t++){
            int dy = t/3 - 1, dx = t - (t/3)*3 - 1;
            if ((unsigned)(h0+dy) < BEV && (unsigned)(w0+dx) < BEV) mA[i] |= 1u << t;
            if ((unsigned)(h1+dy) < BEV && (unsigned)(w1+dx) < BEV) mB[i] |= 1u << t;
        }
    }

    float4 acc[4][2];
#pragma unroll
    for (int mi = 0; mi < 4; mi++)
#pragma unroll
        for (int j = 0; j < 2; j++) acc[mi][j] = make_float4(0.f,0.f,0.f,0.f);

    float pv[4][4];
    auto gather = [&](int ch){
        int t = ch / 6, icb = ch - t*6;
        int dy = t/3 - 1, dx = t - (t/3)*3 - 1;
        int doff = dy*BEV + dx;
        const float* chbase = g_bev + ((size_t)b*BCIN + icb*32)*BEVHW;
#pragma unroll
        for (int i = 0; i < 4; i++){
            const float* base = chbase + sC[i];
            bool ok0 = (mA[i] >> t) & 1;
            bool ok1 = (mB[i] >> t) & 1;
            int o0 = sO0[i] + doff, o1 = sO1[i] + doff;
            pv[i][0] = ok0 ? __ldg(base + o0) : 0.f;
            pv[i][1] = ok1 ? __ldg(base + o1) : 0.f;
            pv[i][2] = ok0 ? __ldg(base + 4*BEVHW + o0) : 0.f;
            pv[i][3] = ok1 ? __ldg(base + 4*BEVHW + o1) : 0.f;
        }
    };
    auto store_stage = [&](float* buf){
#pragma unroll
        for (int i = 0; i < 4; i++)
            *reinterpret_cast<float4*>(&buf[sSlot[i]*4]) =
                make_float4(pv[i][0], pv[i][1], pv[i][2], pv[i][3]);
    };

    gather(0);
    store_stage(Ast0);
    __syncthreads();

    for (int ch = 0; ch < 54; ch++){
        if (ch < 53) gather(ch + 1);
        const float4* Af = reinterpret_cast<const float4*>((ch & 1) ? Ast1 : Ast0);
        const float4* Bbase = reinterpret_cast<const float4*>(g_w1b);
#pragma unroll
        for (int fk = 0; fk < 4; fk++){
            int k8g = ch*4 + fk;
            uint32_t a[4][4];
#pragma unroll
            for (int mi = 0; mi < 4; mi++){
                float4 av = Af[((wm*4 + mi)*4 + fk)*32 + lane];
                a[mi][0] = __float_as_uint(av.x); a[mi][1] = __float_as_uint(av.y);
                a[mi][2] = __float_as_uint(av.z); a[mi][3] = __float_as_uint(av.w);
            }
            // pair-packed: 1 LDG.128 covers both fn of this warp
            float4 bv = __ldg(Bbase + ((size_t)k8g*32 + lane)*4 + wn);
            uint32_t b0 = __float_as_uint(bv.x), b1 = __float_as_uint(bv.y);
            uint32_t b2 = __float_as_uint(bv.z), b3 = __float_as_uint(bv.w);
#pragma unroll
            for (int mi = 0; mi < 4; mi++){
                mma8(acc[mi][0], a[mi][0],a[mi][1],a[mi][2],a[mi][3], b0,b1);
                mma8(acc[mi][1], a[mi][0],a[mi][1],a[mi][2],a[mi][3], b2,b3);
            }
        }
        if (ch < 53) store_stage(((ch + 1) & 1) ? Ast1 : Ast0);
        __syncthreads();
    }

    // exchange: bias + GELU -> smem in A-frag order (K=64, M=256; overlays both buffers)
    const int g4 = lane >> 2, t4 = lane & 3;
    float* A2 = sbuf;
#pragma unroll
    for (int mi = 0; mi < 4; mi++){
        int fm = wm*4 + mi;
#pragma unroll
        for (int j = 0; j < 2; j++){
            int fn = wn*2 + j;
            float v[4] = {acc[mi][j].x, acc[mi][j].y, acc[mi][j].z, acc[mi][j].w};
#pragma unroll
            for (int q = 0; q < 4; q++){
                int hc = fn*8 + 2*t4 + (q & 1);
                int r2 = g4 + (q >> 1)*8;
                float x = v[q] + __ldg(bb1 + hc);
                float gl = 0.5f * x * (1.f + erff(x * 0.70710678118654752f));
                int l2  = g4*4 + (hc & 3);
                int pos = (r2 >> 3) + 2*((hc & 7) >> 2);
                A2[((fn*16 + fm)*32 + l2)*4 + pos] = to_tf32(gl);
            }
        }
    }
    __syncthreads();

    // 1x1 GEMM: K=64
    float4 acc2[4][2];
#pragma unroll
    for (int mi = 0; mi < 4; mi++)
#pragma unroll
        for (int j = 0; j < 2; j++) acc2[mi][j] = make_float4(0.f,0.f,0.f,0.f);

#pragma unroll
    for (int k8 = 0; k8 < 8; k8++){
        uint32_t a[4][4];
#pragma unroll
        for (int mi = 0; mi < 4; mi++){
            float4 av = reinterpret_cast<const float4*>(A2)[(k8*16 + wm*4 + mi)*32 + lane];
            a[mi][0] = __float_as_uint(av.x); a[mi][1] = __float_as_uint(av.y);
            a[mi][2] = __float_as_uint(av.z); a[mi][3] = __float_as_uint(av.w);
        }
        float4 bv = __ldg(reinterpret_cast<const float4*>(g_w2b) +
                          ((size_t)k8*32 + lane)*4 + wn);
        uint32_t b0 = __float_as_uint(bv.x), b1 = __float_as_uint(bv.y);
        uint32_t b2 = __float_as_uint(bv.z), b3 = __float_as_uint(bv.w);
#pragma unroll
        for (int mi = 0; mi < 4; mi++){
            mma8(acc2[mi][0], a[mi][0],a[mi][1],a[mi][2],a[mi][3], b0,b1);
            mma8(acc2[mi][1], a[mi][0],a[mi][1],a[mi][2],a[mi][3], b2,b3);
        }
    }

    // epilogue: bias + store
#pragma unroll
    for (int mi = 0; mi < 4; mi++){
        int fm = wm*4 + mi;
#pragma unroll
        for (int j = 0; j < 2; j++){
            int fn = wn*2 + j;
            float v[4] = {acc2[mi][j].x, acc2[mi][j].y, acc2[mi][j].z, acc2[mi][j].w};
#pragma unroll
            for (int q = 0; q < 4; q++){
                int oc = fn*8 + 2*t4 + (q & 1);
                int m  = fm*16 + g4 + (q >> 1)*8;
                int h  = hb*8 + (m >> 5);
                int wc = wb*32 + (m & 31);
                if (wc < BEV)
                    out[((size_t)b*BMID + oc)*BEVHW + h*BEV + wc] = v[q] + __ldg(bb2 + oc);
            }
        }
    }
}

// ======================================================================
extern "C" void kernel_launch(void* const* d_in, const int* in_sizes, int n_in,
                              void* d_out, int out_size)
{
    const float* feat   = (const float*)d_in[0];
    const float* dw1    = (const float*)d_in[1];
    const float* db1    = (const float*)d_in[2];
    const float* dgamma = (const float*)d_in[3];
    const float* dbeta  = (const float*)d_in[4];
    const float* dmean  = (const float*)d_in[5];
    const float* dvar   = (const float*)d_in[6];
    const float* dw2    = (const float*)d_in[7];
    const float* db2    = (const float*)d_in[8];
    const float* cw1    = (const float*)d_in[9];
    const float* cb1    = (const float*)d_in[10];
    const float* cgamma = (const float*)d_in[11];
    const float* cbeta  = (const float*)d_in[12];
    const float* cmean  = (const float*)d_in[13];
    const float* cvar   = (const float*)d_in[14];
    const float* cw2    = (const float*)d_in[15];
    const float* cb2    = (const float*)d_in[16];
    const float* bw1    = (const float*)d_in[17];
    const float* bb1    = (const float*)d_in[18];
    const float* bw2    = (const float*)d_in[19];
    const float* bb2    = (const float*)d_in[20];

    float* out = (float*)d_out;
    float* depth_logits = out + (long)NB*BMID*BEVHW;

    cudaFuncSetAttribute(bev_mma, cudaFuncAttributeMaxDynamicSharedMemorySize, 65536);

    prep_big<<<dim3(2304, 3), 256>>>(dw1, cw1, bw1);
    prep_small<<<dim3((NCAM*CIN*HW/4 + 255)/256, 4), 256>>>(dw2, cw2, bw2, feat);

    // heads (softmax-sum over depth bins == 1, so pooled == context exactly)
    head3_mma<<<dim3(22, NCAM, 2), 512>>>(
        db1, dgamma, dbeta, dmean, dvar,
        cb1, cgamma, cbeta, cmean, cvar);
    head1_mma<<<dim3(22, NCAM, 2), 256>>>(db2, cb2, depth_logits);

    {
        long total = (long)NB*BCIN*BEV*100;
        upsample_k<<<(int)((total + 255)/256), 256>>>();
    }

    bev_mma<<<dim3(13, 50, NB), 512, 65536>>>(bb1, bb2, out);
}

// round 10
// speedup vs baseline: 1.7641x; 1.7641x over previous
#include <cuda_runtime.h>
#include <stdint.h>
#include <math.h>

#define NCAM 12
#define CIN 256
#define FH 32
#define FW 88
#define HW 2816
#define DBINS 41
#define CTXC 32
#define NB 2
#define BCIN 192
#define BEV 400
#define BMID 64
#define BEVHW 160000

// ---------------- scratch (device globals; no allocations) ----------------
// B-frag arrays, K-PAIR-PACKED: float4 @ ((k8>>1)*NF + fn)*32 + lane =
//   {b0,b1 of k8 even; b0,b1 of k8 odd}  -> lane-contiguous, coalesced
__device__ __align__(16) float g_w1d[288*32*32*2];
__device__ __align__(16) float g_w1c[288*32*32*2];
__device__ __align__(16) float g_w1b[216*8*32*2];
__device__ __align__(16) float g_w2d[32*8*32*2];
__device__ __align__(16) float g_w2c[32*8*32*2];
__device__ __align__(16) float g_w2b[8*8*32*2];
__device__ __align__(16) float g_hidA[(size_t)2*NCAM*22*128*256];
__device__ __align__(16) float g_context[NCAM*CTXC*HW];
__device__ __align__(16) float g_bev[(size_t)NB*BCIN*BEVHW];
__device__ __align__(16) float g_featr[(size_t)NCAM*CIN*HW];   // tf32-rounded feat

// ---------------- helpers ----------------
__device__ __forceinline__ uint32_t f2tf32(float x){
    uint32_t r; asm("cvt.rna.tf32.f32 %0, %1;" : "=r"(r) : "f"(x)); return r;
}
__device__ __forceinline__ float to_tf32(float x){ return __uint_as_float(f2tf32(x)); }
__device__ __forceinline__ void mma8(float4& d,
    uint32_t a0, uint32_t a1, uint32_t a2, uint32_t a3,
    uint32_t b0, uint32_t b1)
{
    asm volatile("mma.sync.aligned.m16n8k8.row.col.f32.tf32.tf32.f32 "
        "{%0,%1,%2,%3}, {%4,%5,%6,%7}, {%8,%9}, {%0,%1,%2,%3};"
        : "+f"(d.x), "+f"(d.y), "+f"(d.z), "+f"(d.w)
        : "r"(a0), "r"(a1), "r"(a2), "r"(a3), "r"(b0), "r"(b1));
}

// ============ prep 1: conv3x3 weights -> K-pair-packed B-frag order ============
// k = t*IC + ic. l=(oc&7)*4+(k&3), pos=(k&7)>>2, fn=oc>>3
// out[ (((k>>4)*NF + fn)*32 + l)*4 + ((k>>3)&1)*2 + pos ]
__global__ void prep_big(const float* __restrict__ dw1, const float* __restrict__ cw1,
                         const float* __restrict__ bw1)
{
    const int y = blockIdx.y;
    const float* w; float* o; int OC, IC;
    if (y == 0){ w = dw1; o = g_w1d; OC = 256; IC = 256; }
    else if (y == 1){ w = cw1; o = g_w1c; OC = 256; IC = 256; }
    else { w = bw1; o = g_w1b; OC = 64; IC = 192; }
    int idx = blockIdx.x*256 + threadIdx.x;
    if (idx >= OC*IC*9) return;
    int oc = idx / (IC*9);
    int rr = idx - oc*(IC*9);
    int ic = rr / 9;
    int t  = rr - ic*9;
    int k  = t*IC + ic;
    int NF = OC >> 3;
    int fn = oc >> 3;
    int l = (oc & 7)*4 + (k & 3);
    int pos = (k & 7) >> 2;
    o[((((size_t)(k>>4)*NF + fn)*32 + l)*4) + ((k>>3)&1)*2 + pos] = to_tf32(w[idx]);
}

// ============ prep 2: 1x1 weights -> K-pair-packed frags (pad 64) + feat rounding ============
__global__ void prep_small(const float* __restrict__ dw2, const float* __restrict__ cw2,
                           const float* __restrict__ bw2, const float* __restrict__ feat)
{
    const int y = blockIdx.y;
    if (y == 3){
        int i = blockIdx.x*256 + threadIdx.x;        // float4 index
        if (i < (NCAM*CIN*HW)/4){
            float4 v = __ldg(reinterpret_cast<const float4*>(feat) + i);
            v.x = to_tf32(v.x); v.y = to_tf32(v.y);
            v.z = to_tf32(v.z); v.w = to_tf32(v.w);
            reinterpret_cast<float4*>(g_featr)[i] = v;
        }
        return;
    }
    const float* w; float* o; int OC, K;
    if (y == 0){ w = dw2; o = g_w2d; OC = DBINS; K = 256; }
    else if (y == 1){ w = cw2; o = g_w2c; OC = CTXC; K = 256; }
    else { w = bw2; o = g_w2b; OC = 64; K = 64; }
    int idx = blockIdx.x*256 + threadIdx.x;
    if (idx >= 64*K) return;
    int oc = idx / K, k = idx - oc*K;
    float v = (oc < OC) ? to_tf32(w[(size_t)oc*K + k]) : 0.f;
    int fn = oc >> 3;                                  // NF = 8
    int l = (oc & 7)*4 + (k & 3);
    int pos = (k & 7) >> 2;
    o[((((size_t)(k>>4)*8 + fn)*32 + l)*4) + ((k>>3)&1)*2 + pos] = v;
}

// ============ HEAD conv3x3 + BN + ReLU -> g_hidA (frag order) ============
// grid (22, 12, 2), 512 threads. M=128 px, N=256, K=2304 (72 chunks of 32).
__global__ __launch_bounds__(512) void head3_mma(
    const float* __restrict__ db1, const float* __restrict__ dg,
    const float* __restrict__ dbt, const float* __restrict__ dm, const float* __restrict__ dv,
    const float* __restrict__ cb1, const float* __restrict__ cg,
    const float* __restrict__ cbt, const float* __restrict__ cm, const float* __restrict__ cv)
{
    __shared__ __align__(16) float Abuf[2][4096];
    __shared__ float sS[256], sT[256];

    const int tid = threadIdx.x;
    const int pb = blockIdx.x, n = blockIdx.y, head = blockIdx.z;
    const float* W1 = head ? g_w1c : g_w1d;

    if (tid < 256){
        int c = tid;
        float gam = head ? cg[c]  : dg[c];
        float var = head ? cv[c]  : dv[c];
        float bet = head ? cbt[c] : dbt[c];
        float mu  = head ? cm[c]  : dm[c];
        float bi  = head ? cb1[c] : db1[c];
        float s = gam * rsqrtf(var + 1e-5f);
        sS[c] = s;
        sT[c] = bet + (bi - mu)*s;
    }

    const int lane = tid & 31;
    const int wrp  = tid >> 5;
    const int wm = wrp & 3;          // m-warp: fm = wm*2 + mi
    const int wn = wrp >> 2;         // n-warp: fn = wn*8 + j

    // staging precompute: 2 slots per thread, 9-bit tap-validity masks
    int sOff0[2], sOff1[2], sIc[2], sSlot[2];
    uint32_t mA[2], mB[2];
#pragma unroll
    for (int i = 0; i < 2; i++){
        int s = tid + i*512;
        int fm = s >> 7, fk = (s >> 5) & 3, l = s & 31;
        int m0 = fm*16 + (l >> 2);
        int px0 = pb*128 + m0, px1 = px0 + 8;
        int h0 = px0 / FW, w0 = px0 % FW;
        int h1 = px1 / FW, w1 = px1 % FW;
        sOff0[i] = px0; sOff1[i] = px1;
        sIc[i] = fk*8 + (l & 3);
        sSlot[i] = s;
        mA[i] = 0; mB[i] = 0;
#pragma unroll
        for (int t = 0; t < 9; t++){
            int dy = t/3 - 1, dx = t - (t/3)*3 - 1;
            if ((unsigned)(h0+dy) < FH && (unsigned)(w0+dx) < FW) mA[i] |= 1u << t;
            if ((unsigned)(h1+dy) < FH && (unsigned)(w1+dx) < FW) mB[i] |= 1u << t;
        }
    }

    float4 acc[2][8];
#pragma unroll
    for (int mi = 0; mi < 2; mi++)
#pragma unroll
        for (int j = 0; j < 8; j++) acc[mi][j] = make_float4(0.f,0.f,0.f,0.f);

    float pv[2][4];
    auto gather = [&](int ch){
        int t = ch >> 3, icb = ch & 7;
        int dy = t/3 - 1, dx = t - (t/3)*3 - 1;
        int doff = dy*FW + dx;
#pragma unroll
        for (int i = 0; i < 2; i++){
            const float* base = g_featr + ((size_t)n*CIN + icb*32 + sIc[i])*HW;
            bool ok0 = (mA[i] >> t) & 1;
            bool ok1 = (mB[i] >> t) & 1;
            int o0 = sOff0[i] + doff, o1 = sOff1[i] + doff;
            pv[i][0] = ok0 ? __ldg(base + o0) : 0.f;
            pv[i][1] = ok1 ? __ldg(base + o1) : 0.f;
            pv[i][2] = ok0 ? __ldg(base + 4*HW + o0) : 0.f;
            pv[i][3] = ok1 ? __ldg(base + 4*HW + o1) : 0.f;
        }
    };
    auto store_stage = [&](int buf){
#pragma unroll
        for (int i = 0; i < 2; i++)
            *reinterpret_cast<float4*>(&Abuf[buf][sSlot[i]*4]) =
                make_float4(pv[i][0], pv[i][1], pv[i][2], pv[i][3]);
    };

    gather(0);
    store_stage(0);
    __syncthreads();

    for (int ch = 0; ch < 72; ch++){
        if (ch < 71) gather(ch + 1);
        const float4* Af = reinterpret_cast<const float4*>(&Abuf[ch & 1][0]);
        const float4* B4 = reinterpret_cast<const float4*>(W1);
#pragma unroll
        for (int fkp = 0; fkp < 2; fkp++){
            // A frags for both fk of this pair
            uint32_t a[2][2][4];
#pragma unroll
            for (int fki = 0; fki < 2; fki++){
                int fk = fkp*2 + fki;
#pragma unroll
                for (int mi = 0; mi < 2; mi++){
                    float4 av = Af[((wm*2 + mi)*4 + fk)*32 + lane];
                    a[fki][mi][0] = __float_as_uint(av.x); a[fki][mi][1] = __float_as_uint(av.y);
                    a[fki][mi][2] = __float_as_uint(av.z); a[fki][mi][3] = __float_as_uint(av.w);
                }
            }
            // K-pair-packed: one LDG.128 = both k-steps of one fn (lane-contiguous)
            const float4* Bf = B4 + ((size_t)(ch*2 + fkp)*32 + wn*8)*32 + lane;
#pragma unroll
            for (int j = 0; j < 8; j++){
                float4 bv = __ldg(Bf + j*32);
                uint32_t b0 = __float_as_uint(bv.x), b1 = __float_as_uint(bv.y);
                uint32_t b2 = __float_as_uint(bv.z), b3 = __float_as_uint(bv.w);
                mma8(acc[0][j], a[0][0][0],a[0][0][1],a[0][0][2],a[0][0][3], b0,b1);
                mma8(acc[1][j], a[0][1][0],a[0][1][1],a[0][1][2],a[0][1][3], b0,b1);
                mma8(acc[0][j], a[1][0][0],a[1][0][1],a[1][0][2],a[1][0][3], b2,b3);
                mma8(acc[1][j], a[1][1][0],a[1][1][1],a[1][1][2],a[1][1][3], b2,b3);
            }
        }
        if (ch < 71) store_stage((ch + 1) & 1);
        __syncthreads();
    }

    // epilogue: BN + ReLU, write in stage-2 A-fragment order
    const int g4 = lane >> 2, t4 = lane & 3;
    float* dst = g_hidA + ((size_t)(head*NCAM + n)*22 + pb)*32768;
#pragma unroll
    for (int mi = 0; mi < 2; mi++){
        int fm = wm*2 + mi;
#pragma unroll
        for (int j = 0; j < 8; j++){
            int fn = wn*8 + j;
            float v[4] = {acc[mi][j].x, acc[mi][j].y, acc[mi][j].z, acc[mi][j].w};
#pragma unroll
            for (int q = 0; q < 4; q++){
                int oc = fn*8 + 2*t4 + (q & 1);
                int r2 = g4 + (q >> 1)*8;
                float val = fmaxf(fmaf(v[q], sS[oc], sT[oc]), 0.f);
                int l2  = g4*4 + (oc & 3);
                int pos = (r2 >> 3) + 2*((oc & 7) >> 2);
                dst[(size_t)((fn*8 + fm)*32 + l2)*4 + pos] = to_tf32(val);
            }
        }
    }
}

// ============ HEAD 1x1 (256 -> 41/32), reads g_hidA frags directly ============
__global__ __launch_bounds__(256) void head1_mma(
    const float* __restrict__ db2, const float* __restrict__ cb2,
    float* __restrict__ depth_out)
{
    const int tid = threadIdx.x;
    const int pb = blockIdx.x, n = blockIdx.y, head = blockIdx.z;
    const int lane = tid & 31, wrp = tid >> 5;
    const int wm = wrp & 3, wn = wrp >> 2;   // fn = wn*4 + j

    const float* W2 = head ? g_w2c : g_w2d;
    const float* Ab = g_hidA + ((size_t)(head*NCAM + n)*22 + pb)*32768;

    float4 acc[2][4];
#pragma unroll
    for (int mi = 0; mi < 2; mi++)
#pragma unroll
        for (int j = 0; j < 4; j++) acc[mi][j] = make_float4(0.f,0.f,0.f,0.f);

#pragma unroll 2
    for (int kp = 0; kp < 16; kp++){
        uint32_t a[2][2][4];
#pragma unroll
        for (int ki = 0; ki < 2; ki++){
            int k8 = kp*2 + ki;
#pragma unroll
            for (int mi = 0; mi < 2; mi++){
                float4 av = __ldg(reinterpret_cast<const float4*>(Ab) +
                                  (k8*8 + wm*2 + mi)*32 + lane);
                a[ki][mi][0] = __float_as_uint(av.x); a[ki][mi][1] = __float_as_uint(av.y);
                a[ki][mi][2] = __float_as_uint(av.z); a[ki][mi][3] = __float_as_uint(av.w);
            }
        }
        const float4* Bf = reinterpret_cast<const float4*>(W2) +
                           ((size_t)kp*8 + wn*4)*32 + lane;
#pragma unroll
        for (int j = 0; j < 4; j++){
            float4 bv = __ldg(Bf + j*32);
            uint32_t b0 = __float_as_uint(bv.x), b1 = __float_as_uint(bv.y);
            uint32_t b2 = __float_as_uint(bv.z), b3 = __float_as_uint(bv.w);
            mma8(acc[0][j], a[0][0][0],a[0][0][1],a[0][0][2],a[0][0][3], b0,b1);
            mma8(acc[1][j], a[0][1][0],a[0][1][1],a[0][1][2],a[0][1][3], b0,b1);
            mma8(acc[0][j], a[1][0][0],a[1][0][1],a[1][0][2],a[1][0][3], b2,b3);
            mma8(acc[1][j], a[1][1][0],a[1][1][1],a[1][1][2],a[1][1][3], b2,b3);
        }
    }

    const int g4 = lane >> 2, t4 = lane & 3;
#pragma unroll
    for (int mi = 0; mi < 2; mi++){
        int fm = wm*2 + mi;
#pragma unroll
        for (int j = 0; j < 4; j++){
            int fn = wn*4 + j;
            float v[4] = {acc[mi][j].x, acc[mi][j].y, acc[mi][j].z, acc[mi][j].w};
#pragma unroll
            for (int q = 0; q < 4; q++){
                int oc = fn*8 + 2*t4 + (q & 1);
                int px = pb*128 + fm*16 + g4 + (q >> 1)*8;
                if (head == 0){
                    if (oc < DBINS)
                        depth_out[((size_t)n*DBINS + oc)*HW + px] = v[q] + __ldg(db2 + oc);
                } else {
                    if (oc < CTXC)
                        g_context[((size_t)n*CTXC + oc)*HW + px] = v[q] + __ldg(cb2 + oc);
                }
            }
        }
    }
}

// ============ bilinear upsample (half-pixel, clamp), writes tf32-rounded ============
__global__ __launch_bounds__(256) void upsample_k()
{
    long idx = (long)blockIdx.x * 256 + threadIdx.x;
    const long total = (long)NB*BCIN*BEV*100;
    if (idx >= total) return;
    int q = (int)(idx % 100);
    long rr = idx / 100;
    int i = (int)(rr % BEV);  rr /= BEV;
    int g = (int)(rr % BCIN);
    int b = (int)(rr / BCIN);

    float sy = (i + 0.5f) * (32.f/400.f) - 0.5f;
    int y0 = (int)floorf(sy); float fy = sy - (float)y0;
    int y1 = y0 + 1;
    y0 = max(0, min(FH-1, y0)); y1 = max(0, min(FH-1, y1));
    const float* p0 = g_context + ((long)b*BCIN + g)*HW + y0*FW;
    const float* p1 = g_context + ((long)b*BCIN + g)*HW + y1*FW;

    float4 o; float* ov = &o.x;
#pragma unroll
    for (int c = 0; c < 4; c++){
        int j = q*4 + c;
        float sx = (j + 0.5f) * (88.f/400.f) - 0.5f;
        int x0 = (int)floorf(sx); float fx = sx - (float)x0;
        int x1 = x0 + 1;
        x0 = max(0, min(FW-1, x0)); x1 = max(0, min(FW-1, x1));
        float t  = p0[x0] + (p0[x1] - p0[x0]) * fx;
        float bo = p1[x0] + (p1[x1] - p1[x0]) * fx;
        ov[c] = to_tf32(t + (bo - t) * fy);
    }
    *reinterpret_cast<float4*>(&g_bev[(((long)b*BCIN + g)*BEV + i)*BEV + q*4]) = o;
}

// ============ BEV conv3x3 + GELU + 1x1, fused mma ============
// grid (13, 50, 2), 512 threads. Tile = 8 rows x 32 cols = 256 px. N=64, K=1728.
__global__ __launch_bounds__(512) void bev_mma(
    const float* __restrict__ bb1, const float* __restrict__ bb2,
    float* __restrict__ out)
{
    extern __shared__ __align__(16) float sbuf[];
    float* Ast0 = sbuf;
    float* Ast1 = sbuf + 8192;

    const int tid = threadIdx.x;
    const int wb = blockIdx.x, hb = blockIdx.y, b = blockIdx.z;
    const int lane = tid & 31, wrp = tid >> 5;
    const int wm = wrp & 3;          // m-warp: fm = wm*4 + mi (mi 0..3)
    const int wn = wrp >> 2;         // n-warp 0..3: fn = wn*2 + j

    // staging precompute: 4 slots per thread (2048 slots total)
    int sO0[4], sO1[4], sC[4], sSlot[4];
    uint32_t mA[4], mB[4];
#pragma unroll
    for (int i = 0; i < 4; i++){
        int s = tid + i*512;
        int fm = s >> 7, fk = (s >> 5) & 3, l = s & 31;
        int m0 = fm*16 + (l >> 2), m1 = m0 + 8;
        int h0 = hb*8 + (m0 >> 5), w0 = wb*32 + (m0 & 31);
        int h1 = hb*8 + (m1 >> 5), w1 = wb*32 + (m1 & 31);
        sO0[i] = h0*BEV + w0; sO1[i] = h1*BEV + w1;
        sC[i] = (fk*8 + (l & 3))*BEVHW;
        sSlot[i] = s;
        mA[i] = 0; mB[i] = 0;
#pragma unroll
        for (int t = 0; t < 9; t++){
            int dy = t/3 - 1, dx = t - (t/3)*3 - 1;
            if ((unsigned)(h0+dy) < BEV && (unsigned)(w0+dx) < BEV) mA[i] |= 1u << t;
            if ((unsigned)(h1+dy) < BEV && (unsigned)(w1+dx) < BEV) mB[i] |= 1u << t;
        }
    }

    float4 acc[4][2];
#pragma unroll
    for (int mi = 0; mi < 4; mi++)
#pragma unroll
        for (int j = 0; j < 2; j++) acc[mi][j] = make_float4(0.f,0.f,0.f,0.f);

    float pv[4][4];
    auto gather = [&](int ch){
        int t = ch / 6, icb = ch - t*6;
        int dy = t/3 - 1, dx = t - (t/3)*3 - 1;
        int doff = dy*BEV + dx;
        const float* chbase = g_bev + ((size_t)b*BCIN + icb*32)*BEVHW;
#pragma unroll
        for (int i = 0; i < 4; i++){
            const float* base = chbase + sC[i];
            bool ok0 = (mA[i] >> t) & 1;
            bool ok1 = (mB[i] >> t) & 1;
            int o0 = sO0[i] + doff, o1 = sO1[i] + doff;
            pv[i][0] = ok0 ? __ldg(base + o0) : 0.f;
            pv[i][1] = ok1 ? __ldg(base + o1) : 0.f;
            pv[i][2] = ok0 ? __ldg(base + 4*BEVHW + o0) : 0.f;
            pv[i][3] = ok1 ? __ldg(base + 4*BEVHW + o1) : 0.f;
        }
    };
    auto store_stage = [&](float* buf){
#pragma unroll
        for (int i = 0; i < 4; i++)
            *reinterpret_cast<float4*>(&buf[sSlot[i]*4]) =
                make_float4(pv[i][0], pv[i][1], pv[i][2], pv[i][3]);
    };

    gather(0);
    store_stage(Ast0);
    __syncthreads();

    for (int ch = 0; ch < 54; ch++){
        if (ch < 53) gather(ch + 1);
        const float4* Af = reinterpret_cast<const float4*>((ch & 1) ? Ast1 : Ast0);
        const float4* B4 = reinterpret_cast<const float4*>(g_w1b);
#pragma unroll
        for (int fkp = 0; fkp < 2; fkp++){
            uint32_t a[2][4][4];
#pragma unroll
            for (int fki = 0; fki < 2; fki++){
                int fk = fkp*2 + fki;
#pragma unroll
                for (int mi = 0; mi < 4; mi++){
                    float4 av = Af[((wm*4 + mi)*4 + fk)*32 + lane];
                    a[fki][mi][0] = __float_as_uint(av.x); a[fki][mi][1] = __float_as_uint(av.y);
                    a[fki][mi][2] = __float_as_uint(av.z); a[fki][mi][3] = __float_as_uint(av.w);
                }
            }
            const float4* Bf = B4 + ((size_t)(ch*2 + fkp)*8 + wn*2)*32 + lane;
#pragma unroll
            for (int j = 0; j < 2; j++){
                float4 bv = __ldg(Bf + j*32);
                uint32_t b0 = __float_as_uint(bv.x), b1 = __float_as_uint(bv.y);
                uint32_t b2 = __float_as_uint(bv.z), b3 = __float_as_uint(bv.w);
#pragma unroll
                for (int mi = 0; mi < 4; mi++){
                    mma8(acc[mi][j], a[0][mi][0],a[0][mi][1],a[0][mi][2],a[0][mi][3], b0,b1);
                    mma8(acc[mi][j], a[1][mi][0],a[1][mi][1],a[1][mi][2],a[1][mi][3], b2,b3);
                }
            }
        }
        if (ch < 53) store_stage(((ch + 1) & 1) ? Ast1 : Ast0);
        __syncthreads();
    }

    // exchange: bias + GELU -> smem in A-frag order (K=64, M=256; overlays both buffers)
    const int g4 = lane >> 2, t4 = lane & 3;
    float* A2 = sbuf;
#pragma unroll
    for (int mi = 0; mi < 4; mi++){
        int fm = wm*4 + mi;
#pragma unroll
        for (int j = 0; j < 2; j++){
            int fn = wn*2 + j;
            float v[4] = {acc[mi][j].x, acc[mi][j].y, acc[mi][j].z, acc[mi][j].w};
#pragma unroll
            for (int q = 0; q < 4; q++){
                int hc = fn*8 + 2*t4 + (q & 1);
                int r2 = g4 + (q >> 1)*8;
                float x = v[q] + __ldg(bb1 + hc);
                float gl = 0.5f * x * (1.f + erff(x * 0.70710678118654752f));
                int l2  = g4*4 + (hc & 3);
                int pos = (r2 >> 3) + 2*((hc & 7) >> 2);
                A2[((fn*16 + fm)*32 + l2)*4 + pos] = to_tf32(gl);
            }
        }
    }
    __syncthreads();

    // 1x1 GEMM: K=64 (4 k-pairs)
    float4 acc2[4][2];
#pragma unroll
    for (int mi = 0; mi < 4; mi++)
#pragma unroll
        for (int j = 0; j < 2; j++) acc2[mi][j] = make_float4(0.f,0.f,0.f,0.f);

#pragma unroll
    for (int kp = 0; kp < 4; kp++){
        uint32_t a[2][4][4];
#pragma unroll
        for (int ki = 0; ki < 2; ki++){
            int k8 = kp*2 + ki;
#pragma unroll
            for (int mi = 0; mi < 4; mi++){
                float4 av = reinterpret_cast<const float4*>(A2)[(k8*16 + wm*4 + mi)*32 + lane];
                a[ki][mi][0] = __float_as_uint(av.x); a[ki][mi][1] = __float_as_uint(av.y);
                a[ki][mi][2] = __float_as_uint(av.z); a[ki][mi][3] = __float_as_uint(av.w);
            }
        }
        const float4* Bf = reinterpret_cast<const float4*>(g_w2b) +
                           ((size_t)kp*8 + wn*2)*32 + lane;
#pragma unroll
        for (int j = 0; j < 2; j++){
            float4 bv = __ldg(Bf + j*32);
            uint32_t b0 = __float_as_uint(bv.x), b1 = __float_as_uint(bv.y);
            uint32_t b2 = __float_as_uint(bv.z), b3 = __float_as_uint(bv.w);
#pragma unroll
            for (int mi = 0; mi < 4; mi++){
                mma8(acc2[mi][j], a[0][mi][0],a[0][mi][1],a[0][mi][2],a[0][mi][3], b0,b1);
                mma8(acc2[mi][j], a[1][mi][0],a[1][mi][1],a[1][mi][2],a[1][mi][3], b2,b3);
            }
        }
    }

    // epilogue: bias + store
#pragma unroll
    for (int mi = 0; mi < 4; mi++){
        int fm = wm*4 + mi;
#pragma unroll
        for (int j = 0; j < 2; j++){
            int fn = wn*2 + j;
            float v[4] = {acc2[mi][j].x, acc2[mi][j].y, acc2[mi][j].z, acc2[mi][j].w};
#pragma unroll
            for (int q = 0; q < 4; q++){
                int oc = fn*8 + 2*t4 + (q & 1);
                int m  = fm*16 + g4 + (q >> 1)*8;
                int h  = hb*8 + (m >> 5);
                int wc = wb*32 + (m & 31);
                if (wc < BEV)
                    out[((size_t)b*BMID + oc)*BEVHW + h*BEV + wc] = v[q] + __ldg(bb2 + oc);
            }
        }
    }
}

// ======================================================================
extern "C" void kernel_launch(void* const* d_in, const int* in_sizes, int n_in,
                              void* d_out, int out_size)
{
    const float* feat   = (const float*)d_in[0];
    const float* dw1    = (const float*)d_in[1];
    const float* db1    = (const float*)d_in[2];
    const float* dgamma = (const float*)d_in[3];
    const float* dbeta  = (const float*)d_in[4];
    const float* dmean  = (const float*)d_in[5];
    const float* dvar   = (const float*)d_in[6];
    const float* dw2    = (const float*)d_in[7];
    const float* db2    = (const float*)d_in[8];
    const float* cw1    = (const float*)d_in[9];
    const float* cb1    = (const float*)d_in[10];
    const float* cgamma = (const float*)d_in[11];
    const float* cbeta  = (const float*)d_in[12];
    const float* cmean  = (const float*)d_in[13];
    const float* cvar   = (const float*)d_in[14];
    const float* cw2    = (const float*)d_in[15];
    const float* cb2    = (const float*)d_in[16];
    const float* bw1    = (const float*)d_in[17];
    const float* bb1    = (const float*)d_in[18];
    const float* bw2    = (const float*)d_in[19];
    const float* bb2    = (const float*)d_in[20];

    float* out = (float*)d_out;
    float* depth_logits = out + (long)NB*BMID*BEVHW;

    cudaFuncSetAttribute(bev_mma, cudaFuncAttributeMaxDynamicSharedMemorySize, 65536);

    prep_big<<<dim3(2304, 3), 256>>>(dw1, cw1, bw1);
    prep_small<<<dim3((NCAM*CIN*HW/4 + 255)/256, 4), 256>>>(dw2, cw2, bw2, feat);

    // heads (softmax-sum over depth bins == 1, so pooled == context exactly)
    head3_mma<<<dim3(22, NCAM, 2), 512>>>(
        db1, dgamma, dbeta, dmean, dvar,
        cb1, cgamma, cbeta, cmean, cvar);
    head1_mma<<<dim3(22, NCAM, 2), 256>>>(db2, cb2, depth_logits);

    {
        long total = (long)NB*BCIN*BEV*100;
        upsample_k<<<(int)((total + 255)/256), 256>>>();
    }

    bev_mma<<<dim3(13, 50, NB), 512, 65536>>>(bb1, bb2, out);
}